// round 4
// baseline (speedup 1.0000x reference)
#include <cuda_runtime.h>
#include <cstdint>

#define B_   64
#define TT   512
#define VV   32
#define CC   16          // chunks per batch
#define LL   32          // steps per chunk (TT/CC)
#define NSTG 4
#define NTHR 128
#define F_LOG2E 1.4426950408889634f
#define F_LN2   0.6931471805599453f

typedef unsigned long long ull;

// scratch: per (b, chunk) product matrix + renorm shift + numerator partial
__device__ float g_P[B_*CC*VV*VV];   // 4 MB
__device__ float g_A[B_*CC];
__device__ float g_num[B_*CC];

__device__ __forceinline__ float ex2f_(float x){ float y; asm("ex2.approx.ftz.f32 %0, %1;" : "=f"(y) : "f"(x)); return y; }
__device__ __forceinline__ float lg2f_(float x){ float y; asm("lg2.approx.ftz.f32 %0, %1;" : "=f"(y) : "f"(x)); return y; }
__device__ __forceinline__ ull fma2_(ull a, ull b, ull c){ ull r; asm("fma.rn.f32x2 %0, %1, %2, %3;" : "=l"(r) : "l"(a), "l"(b), "l"(c)); return r; }
__device__ __forceinline__ ull pack2_(float lo, float hi){ ull r; asm("mov.b64 %0, {%1, %2};" : "=l"(r) : "f"(lo), "f"(hi)); return r; }
__device__ __forceinline__ void unpack2_(ull v, float& lo, float& hi){ asm("mov.b64 {%0, %1}, %2;" : "=f"(lo), "=f"(hi) : "l"(v)); }
__device__ __forceinline__ void cpasync16(float* s, const float* g){
  uint32_t sa = (uint32_t)__cvta_generic_to_shared(s);
  asm volatile("cp.async.cg.shared.global [%0], [%1], 16;" :: "r"(sa), "l"(g));
}
__device__ __forceinline__ int tgt_is64(const int* t32){
  int is64 = 1;
  #pragma unroll
  for (int k = 1; k < 64; k += 2) if (t32[k] != 0) is64 = 0;
  return is64;
}

// ============================ Phase 1 ============================
// CTA (b,c): P_c = E_{cL} * E_{cL+1} * ... * E_{cL+L-1}   (32x32, linear space,
// per-step exact power-of-2 renorm; shift accumulated in A). Also numerator partial.
__global__ __launch_bounds__(NTHR)
void crf_phase1(const float* __restrict__ scores,
                const void*  __restrict__ targets_raw,
                const float* __restrict__ w_tx,
                const float* __restrict__ w_dur)
{
  __shared__ __align__(16) float tile[NSTG][VV*VV];   // raw score tiles (cp.async)
  __shared__ __align__(16) float E_sm[2][VV*VV];      // exp'd tile, [i][j] row-major
  __shared__ __align__(16) float P_sm[2][VV*VV];      // running product, [from][to]
  __shared__ __align__(16) float craw[VV*VV];
  __shared__ int tg[LL+1];

  const int blk = blockIdx.x;
  const int b = blk >> 4, c = blk & 15;
  const int tid = threadIdx.x;
  const int j  = tid & 31;      // "to" column
  const int r0 = (tid >> 5) * 8; // warp owns "from" rows r0..r0+7
  const float* sb = scores + ((size_t)b*TT + (size_t)c*LL) * (VV*VV);

  for (int k = tid; k < VV*VV; k += NTHR) craw[k] = w_tx[k] + w_dur[k];
  {
    const int* t32 = (const int*)targets_raw;
    const int tb = b*(TT+1) + c*LL;
    if (tid <= LL)
      tg[tid] = tgt_is64(t32) ? (int)((const long long*)targets_raw)[tb+tid] : t32[tb+tid];
  }

  // cp.async prologue: tiles 0..2
  #pragma unroll
  for (int p = 0; p < NSTG-1; ++p){
    cpasync16(&tile[p][tid*8],     sb + p*VV*VV + tid*8);
    cpasync16(&tile[p][tid*8 + 4], sb + p*VV*VV + tid*8 + 4);
    asm volatile("cp.async.commit_group;");
  }

  float c2own[8];        // (w_tx+w_dur)*log2e for my 8 contiguous cells
  #pragma unroll
  for (int k = 0; k < 8; ++k)
    c2own[k] = (w_tx[tid*8+k] + w_dur[tid*8+k]) * F_LOG2E;

  __syncthreads();

  int A = 0; float num = 0.f;

  for (int t = 0; t < LL; ++t){
    asm volatile("cp.async.wait_group %0;" :: "n"(NSTG-2));   // tile t resident
    const int slot = t & (NSTG-1);

    // exp of my OWN 8 elements (same ones this thread cp.async'd -> no sync needed)
    {
      const float* tp = &tile[slot][tid*8];
      float e0 = ex2f_(fmaf(tp[0], F_LOG2E, c2own[0]));
      float e1 = ex2f_(fmaf(tp[1], F_LOG2E, c2own[1]));
      float e2 = ex2f_(fmaf(tp[2], F_LOG2E, c2own[2]));
      float e3 = ex2f_(fmaf(tp[3], F_LOG2E, c2own[3]));
      float e4 = ex2f_(fmaf(tp[4], F_LOG2E, c2own[4]));
      float e5 = ex2f_(fmaf(tp[5], F_LOG2E, c2own[5]));
      float e6 = ex2f_(fmaf(tp[6], F_LOG2E, c2own[6]));
      float e7 = ex2f_(fmaf(tp[7], F_LOG2E, c2own[7]));
      float* dst = (t == 0) ? &P_sm[0][tid*8] : &E_sm[t & 1][tid*8];
      *(float4*)dst       = make_float4(e0, e1, e2, e3);
      *(float4*)(dst + 4) = make_float4(e4, e5, e6, e7);
    }

    __syncthreads();   // E_sm[t&1] (or P_sm[0]) complete; prev P_sm write complete

    // prefetch tile t+3 into the slot freed at t-1
    {
      int tl = t + NSTG - 1;
      if (tl < LL){
        float* d = &tile[tl & (NSTG-1)][tid*8];
        const float* g = sb + (size_t)tl*VV*VV + tid*8;
        cpasync16(d, g); cpasync16(d+4, g+4);
      }
      asm volatile("cp.async.commit_group;");
    }

    // numerator partial (raw tile fully visible post-barrier)
    if (tid == 0){
      int idx = tg[t]*VV + tg[t+1];
      num += tile[slot][idx] + craw[idx];
    }

    if (t > 0){
      const int pbR = (t-1) & 1, pbW = t & 1, eb = t & 1;

      // CTA-uniform renorm from exponent of P[0][0]
      float p00 = P_sm[pbR][0];
      int esh = ((__float_as_int(p00) >> 23) & 255) - 127;
      float sc = __int_as_float((127 - esh) << 23);
      A += esh;

      // my E column packed as (i, i+1) pairs
      ull E2[16];
      #pragma unroll
      for (int i2 = 0; i2 < 16; ++i2)
        E2[i2] = pack2_(E_sm[eb][(2*i2)*VV + j], E_sm[eb][(2*i2+1)*VV + j]);

      ull acc[8];
      #pragma unroll
      for (int r = 0; r < 8; ++r) acc[r] = 0ull;

      #pragma unroll
      for (int i4 = 0; i4 < 8; ++i4){
        #pragma unroll
        for (int r = 0; r < 8; ++r){
          // P[r0+r][4*i4 .. 4*i4+3], warp-uniform broadcast, 16B aligned
          ulonglong2 q = *(const ulonglong2*)&P_sm[pbR][(r0+r)*VV + 4*i4];
          acc[r] = fma2_(q.x, E2[2*i4],   acc[r]);
          acc[r] = fma2_(q.y, E2[2*i4+1], acc[r]);
        }
      }

      #pragma unroll
      for (int r = 0; r < 8; ++r){
        float lo, hi; unpack2_(acc[r], lo, hi);
        P_sm[pbW][(r0+r)*VV + j] = (lo + hi) * sc;   // bank = j, conflict-free
      }
    }
  }

  __syncthreads();
  const float* Pf = &P_sm[(LL-1) & 1][0];
  float* gout = &g_P[(size_t)blk * (VV*VV)];
  for (int k = tid; k < VV*VV; k += NTHR) gout[k] = Pf[k];
  if (tid == 0){ g_A[blk] = (float)A; g_num[blk] = num; }
}

// ============================ Phase 2 ============================
// One warp per batch: alpha = exp(w_init); alpha <- alpha * P_c (16 matvecs);
// combine numerator partials; emit log-prob.
__global__ __launch_bounds__(32)
void crf_phase2(const void* __restrict__ targets_raw,
                const float* __restrict__ w_init,
                const float* __restrict__ w_final,
                float* __restrict__ out)
{
  const int b = blockIdx.x;
  const int j = threadIdx.x;

  float alpha = ex2f_(w_init[j] * F_LOG2E);
  float A = 0.f;

  for (int c = 0; c < CC; ++c){
    const float* Pc = &g_P[((size_t)b*CC + c) * (VV*VV)];
    float p[32];
    #pragma unroll
    for (int i = 0; i < 32; ++i) p[i] = Pc[i*VV + j];   // coalesced over lanes

    float a0 = __shfl_sync(0xffffffffu, alpha, 0);
    int esh = ((__float_as_int(a0) >> 23) & 255) - 127;
    esh = esh < -126 ? -126 : (esh > 126 ? 126 : esh);
    alpha *= __int_as_float((127 - esh) << 23);
    A += (float)esh + g_A[b*CC + c];

    float n0 = 0.f, n1 = 0.f, n2 = 0.f, n3 = 0.f;
    #pragma unroll
    for (int i = 0; i < 32; i += 4){
      n0 = fmaf(__shfl_sync(0xffffffffu, alpha, i  ), p[i  ], n0);
      n1 = fmaf(__shfl_sync(0xffffffffu, alpha, i+1), p[i+1], n1);
      n2 = fmaf(__shfl_sync(0xffffffffu, alpha, i+2), p[i+2], n2);
      n3 = fmaf(__shfl_sync(0xffffffffu, alpha, i+3), p[i+3], n3);
    }
    alpha = (n0 + n1) + (n2 + n3);
  }

  float term = alpha * ex2f_(w_final[j] * F_LOG2E);
  #pragma unroll
  for (int off = 16; off; off >>= 1)
    term += __shfl_xor_sync(0xffffffffu, term, off);

  // numerator: sum chunk partials (parallel over lanes) + boundary terms
  float np = (j < CC) ? g_num[b*CC + j] : 0.f;
  #pragma unroll
  for (int off = 16; off; off >>= 1)
    np += __shfl_xor_sync(0xffffffffu, np, off);

  if (j == 0){
    const int* t32 = (const int*)targets_raw;
    int tg0, tgT;
    if (tgt_is64(t32)){
      const long long* t64 = (const long long*)targets_raw;
      tg0 = (int)t64[(size_t)b*(TT+1)];
      tgT = (int)t64[(size_t)b*(TT+1) + TT];
    } else {
      tg0 = t32[b*(TT+1)];
      tgT = t32[b*(TT+1) + TT];
    }
    float num = np + w_init[tg0] + w_final[tgT];
    out[b] = num - F_LN2 * (lg2f_(term) + A);
  }
}

extern "C" void kernel_launch(void* const* d_in, const int* in_sizes, int n_in,
                              void* d_out, int out_size)
{
  const float* scores  = (const float*)d_in[0];
  const void*  targets = d_in[1];
  const float* w_tx    = (const float*)d_in[2];
  const float* w_init  = (const float*)d_in[3];
  const float* w_final = (const float*)d_in[4];
  const float* w_dur   = (const float*)d_in[5];
  float* out = (float*)d_out;

  crf_phase1<<<B_*CC, NTHR>>>(scores, targets, w_tx, w_dur);
  crf_phase2<<<B_, 32>>>(targets, w_init, w_final, out);
}